// round 10
// baseline (speedup 1.0000x reference)
#include <cuda_runtime.h>
#include <math.h>

#define BQ 8
#define HH 96
#define WW 96
#define NPIX (BQ*HH*WW)

// ---------------- scratch (device globals; no allocation allowed) ----------
__device__ float g_wc [9*258*64];   // coord conv weights   [t][ci][oc]
__device__ float g_wo [9*64*24];    // offset conv weights  [t][ci][ocp] (oc padded 18->24)
__device__ float g_wd [9*64*64];    // deform weights       [t][ci][oc]
__device__ float g_wr1[9*64*64];
__device__ float g_wr2[9*64*64];
__device__ float g_bufA[NPIX*64];
__device__ float g_bufB[NPIX*64];
__device__ float g_off [NPIX*18];

// ---------------- packed f32x2 helpers (Blackwell FFMA2 via PTX) -----------
__device__ __forceinline__ unsigned long long pack2(float v) {
    unsigned long long r;
    asm("mov.b64 %0, {%1, %1};" : "=l"(r) : "f"(v));
    return r;
}
__device__ __forceinline__ void fma2(unsigned long long& d,
                                     unsigned long long a, unsigned long long b) {
    asm("fma.rn.f32x2 %0, %1, %2, %3;" : "=l"(d) : "l"(a), "l"(b), "l"(d));
}
__device__ __forceinline__ void unpack2(unsigned long long p, float& lo, float& hi) {
    asm("mov.b64 {%0, %1}, %2;" : "=f"(lo), "=f"(hi) : "l"(p));
}

// ---------------- weight transpose: OIHW -> [t][ci][ocp] -------------------
__global__ void transpose_w(const float* __restrict__ src, float* __restrict__ dst,
                            int OC, int IC, int OCP) {
    int n = 9 * IC * OCP;
    for (int i = blockIdx.x * blockDim.x + threadIdx.x; i < n; i += gridDim.x * blockDim.x) {
        int ocp  = i % OCP;
        int rest = i / OCP;
        int ci   = rest % IC;
        int t    = rest / IC;
        dst[i] = (ocp < OC) ? src[(ocp * IC + ci) * 9 + t] : 0.0f;
    }
}

// ---------------- generic 3x3 conv, NHWC, tiled, oc-split ------------------
// 256 threads: px = tid&127 (8x16 tile), half = tid>>7 selects oc slice.
// MODE 0: bn+relu   MODE 1: coordconv (+coord taps +bias +bn +relu)   MODE 2: +bias only
template<int CINLOOP, int CINT, int COUTP, int COUT, int MODE>
__global__ void __launch_bounds__(256) conv3x3(
    const float* __restrict__ in, int in_stride,
    const float* __restrict__ wT,                 // [9][CINT][COUTP]
    const float* __restrict__ p0, const float* __restrict__ p1,
    const float* __restrict__ p2, const float* __restrict__ p3,
    float* __restrict__ out, int out_stride,
    const float* __restrict__ cbias)
{
    constexpr int OCH = COUTP / 2;                // oc per thread
    static_assert(OCH % 4 == 0, "OCH must be float4 divisible");
    __shared__ float patch[10 * 18 * 36];         // 8x16 tile + halo, 32ch, stride 36
    __shared__ float ws[2][32 * COUTP];           // ping-pong per-tap weights

    const int b    = blockIdx.z;
    const int h0   = blockIdx.y * 8;
    const int w0   = blockIdx.x * 16;
    const int tid  = threadIdx.x;
    const int px   = tid & 127;
    const int half = tid >> 7;
    const int lh   = px >> 4;
    const int lw   = px & 15;

    unsigned long long acc2[OCH / 2];
#pragma unroll
    for (int i = 0; i < OCH / 2; ++i) acc2[i] = 0ull;

    for (int c0 = 0; c0 < CINLOOP; c0 += 32) {
        // ---- load 10x18x32 input patch (zero padded), 36-float stride ----
        for (int p = tid; p < 180; p += 256) {
            int ph = p / 18, pw = p - ph * 18;
            int gh = h0 - 1 + ph, gw = w0 - 1 + pw;
            float* dst = &patch[p * 36];
            if ((unsigned)gh < (unsigned)HH && (unsigned)gw < (unsigned)WW) {
                const float4* src4 =
                    (const float4*)(in + ((b * HH + gh) * WW + gw) * in_stride + c0);
#pragma unroll
                for (int i = 0; i < 8; ++i) ((float4*)dst)[i] = src4[i];
            } else {
#pragma unroll
                for (int i = 0; i < 8; ++i)
                    ((float4*)dst)[i] = make_float4(0.f, 0.f, 0.f, 0.f);
            }
        }
        // ---- stage tap-0 weights into buffer 0 ----
        for (int i = tid * 4; i < 32 * COUTP; i += 256 * 4) {
            *(float4*)&ws[0][i] = *(const float4*)&wT[(0 * CINT + c0) * COUTP + i];
        }
        __syncthreads();

        for (int t = 0; t < 9; ++t) {
            // prefetch next tap's weights into the other buffer (overlaps FFMA2)
            if (t < 8) {
                for (int i = tid * 4; i < 32 * COUTP; i += 256 * 4) {
                    *(float4*)&ws[(t + 1) & 1][i] =
                        *(const float4*)&wT[((t + 1) * CINT + c0) * COUTP + i];
                }
            }
            const int ky = t / 3, kx = t - ky * 3;
            const float4* pr4 =
                (const float4*)&patch[((lh + ky) * 18 + (lw + kx)) * 36];
            const float* wbuf = &ws[t & 1][half * OCH];
#pragma unroll
            for (int g = 0; g < 8; ++g) {         // 4 input channels per group
                float4 v4 = pr4[g];
                float vv[4] = {v4.x, v4.y, v4.z, v4.w};
#pragma unroll
                for (int c = 0; c < 4; ++c) {
                    unsigned long long v2 = pack2(vv[c]);
                    const ulonglong2* w2 =
                        (const ulonglong2*)&wbuf[(4 * g + c) * COUTP];
#pragma unroll
                    for (int j = 0; j < OCH / 4; ++j) {
                        ulonglong2 wv = w2[j];    // 4 weights = 2 packed pairs
                        fma2(acc2[2 * j + 0], v2, wv.x);
                        fma2(acc2[2 * j + 1], v2, wv.y);
                    }
                }
            }
            __syncthreads();   // publish prefetched tap; drain before buffer reuse
        }
    }

    float acc[OCH];
#pragma unroll
    for (int j = 0; j < OCH / 2; ++j) unpack2(acc2[j], acc[2 * j], acc[2 * j + 1]);

    const int h = h0 + lh, w = w0 + lw;

    if constexpr (MODE == 1) {
        // analytic coord channels: ci=256 -> xx, ci=257 -> yy (zero-padded)
#pragma unroll
        for (int t = 0; t < 9; ++t) {
            int ky = t / 3, kx = t - ky * 3;
            int gh = h + ky - 1, gw = w + kx - 1;
            bool inb = (unsigned)gh < (unsigned)HH && (unsigned)gw < (unsigned)WW;
            float xxv = inb ? (-1.f + (2.f / 95.f) * (float)gw) : 0.f;
            float yyv = inb ? (-1.f + (2.f / 95.f) * (float)gh) : 0.f;
            const float* wx = &wT[(t * CINT + 256) * COUTP + half * OCH];
            const float* wy = wx + COUTP;
#pragma unroll
            for (int j = 0; j < OCH; ++j)
                acc[j] += xxv * wx[j] + yyv * wy[j];
        }
    }

    float* op = out + ((b * HH + h) * WW + w) * out_stride + half * OCH;
#pragma unroll
    for (int j = 0; j < OCH; ++j) {
        int oc = half * OCH + j;
        if (oc < COUT) {
            float a = acc[j];
            if constexpr (MODE == 1) a += cbias[oc];
            float r;
            if constexpr (MODE == 2) {
                r = a + p0[oc];  // bias only
            } else {
                float inv = p0[oc] * rsqrtf(p3[oc] + 1e-5f);
                r = a * inv + (p1[oc] - p2[oc] * inv);
                r = fmaxf(r, 0.f);
            }
            op[j] = r;
        }
    }
}

// ---------------- deformable conv (bilinear gather + per-tap GEMM) ---------
// 1 px/thread; ci processed in two 32-ch halves to halve live registers.
__global__ void __launch_bounds__(128) deform_kernel(
    const float* __restrict__ x1, const float* __restrict__ off,
    const float* __restrict__ wT,  // [9][64][64]
    const float* __restrict__ bg, const float* __restrict__ bb,
    const float* __restrict__ bm, const float* __restrict__ bv,
    float* __restrict__ out)
{
    __shared__ float ws[2][64 * 64];               // ping-pong per-tap weights
    const int id = blockIdx.x * 128 + threadIdx.x;   // exactly NPIX threads
    const int w = id % WW;
    const int rest = id / WW;
    const int h = rest % HH;
    const int b = rest / HH;

    unsigned long long acc2[32];
#pragma unroll
    for (int i = 0; i < 32; ++i) acc2[i] = 0ull;

    const float* offp = off + id * 18;

    // stage tap-0 weights
    for (int i = threadIdx.x * 4; i < 4096; i += 512)
        *(float4*)&ws[0][i] = *(const float4*)&wT[i];
    __syncthreads();

    for (int k = 0; k < 9; ++k) {
        // prefetch next tap (overlaps gather + GEMM)
        if (k < 8) {
            for (int i = threadIdx.x * 4; i < 4096; i += 512)
                *(float4*)&ws[(k + 1) & 1][i] =
                    *(const float4*)&wT[(k + 1) * 4096 + i];
        }

        float oy = offp[2 * k + 0];
        float ox = offp[2 * k + 1];
        float py = (float)h + (float)(k / 3 - 1) + oy;
        float px = (float)w + (float)(k % 3 - 1) + ox;
        float y0 = floorf(py), x0 = floorf(px);

        // branchless corner setup: invalid corner -> weight 0 + safe pointer
        float wgtv[4];
        const float* ptrv[4];
#pragma unroll
        for (int corner = 0; corner < 4; ++corner) {
            int dy = corner >> 1, dx = corner & 1;
            float yy = y0 + (float)dy, xx = x0 + (float)dx;
            float wgt = (1.f - fabsf(py - yy)) * (1.f - fabsf(px - xx));
            int iy = (int)yy, ix = (int)xx;
            bool ok = (iy >= 0) && (iy < HH) && (ix >= 0) && (ix < WW) && (wgt > 0.f);
            wgtv[corner] = ok ? wgt : 0.f;
            ptrv[corner] = ok ? (x1 + ((b * HH + iy) * WW + ix) * 64) : x1;
        }

        const float* wbuf = ws[k & 1];
#pragma unroll
        for (int hh = 0; hh < 2; ++hh) {           // two 32-channel halves
            unsigned long long s2[16];
#pragma unroll
            for (int i = 0; i < 16; ++i) s2[i] = 0ull;
#pragma unroll
            for (int corner = 0; corner < 4; ++corner) {
                unsigned long long wg2 = pack2(wgtv[corner]);
                const ulonglong2* src =
                    (const ulonglong2*)(ptrv[corner] + hh * 32);
#pragma unroll
                for (int j = 0; j < 8; ++j) {
                    ulonglong2 v = src[j];
                    fma2(s2[2 * j + 0], wg2, v.x);
                    fma2(s2[2 * j + 1], wg2, v.y);
                }
            }
#pragma unroll
            for (int cp = 0; cp < 16; ++cp) {      // pairs of input channels
                float va, vb;
                unpack2(s2[cp], va, vb);
                unsigned long long a2 = pack2(va);
                unsigned long long b2 = pack2(vb);
                int ci0 = hh * 32 + 2 * cp;
                const ulonglong2* wa = (const ulonglong2*)&wbuf[(ci0 + 0) * 64];
                const ulonglong2* wb = (const ulonglong2*)&wbuf[(ci0 + 1) * 64];
#pragma unroll
                for (int j = 0; j < 16; ++j) {
                    ulonglong2 wva = wa[j];
                    ulonglong2 wvb = wb[j];
                    fma2(acc2[2 * j + 0], a2, wva.x);
                    fma2(acc2[2 * j + 1], a2, wva.y);
                    fma2(acc2[2 * j + 0], b2, wvb.x);
                    fma2(acc2[2 * j + 1], b2, wvb.y);
                }
            }
        }
        __syncthreads();   // publish prefetched tap; drain before buffer reuse
    }

    float acc[64];
#pragma unroll
    for (int j = 0; j < 32; ++j) unpack2(acc2[j], acc[2 * j], acc[2 * j + 1]);

    float* op = out + id * 64;
#pragma unroll
    for (int q = 0; q < 16; ++q) {
        float4 r4;
        float* rr = (float*)&r4;
#pragma unroll
        for (int c = 0; c < 4; ++c) {
            int oc = 4 * q + c;
            float inv = bg[oc] * rsqrtf(bv[oc] + 1e-5f);
            float r = acc[oc] * inv + (bb[oc] - bm[oc] * inv);
            rr[c] = fmaxf(r, 0.f);
        }
        ((float4*)op)[q] = r4;
    }
}

// ---------------- 1x1 conv + sigmoid ---------------------------------------
__global__ void out_kernel(const float* __restrict__ x, const float* __restrict__ ow,
                           const float* __restrict__ ob, float* __restrict__ out)
{
    __shared__ float wsh[64];
    if (threadIdx.x < 64) wsh[threadIdx.x] = ow[threadIdx.x];
    __syncthreads();
    int id = blockIdx.x * blockDim.x + threadIdx.x;
    if (id < NPIX) {
        const float4* xp = (const float4*)(x + id * 64);
        float sum = ob[0];
#pragma unroll
        for (int j = 0; j < 16; ++j) {
            float4 v = xp[j];
            float4 wv = ((float4*)wsh)[j];
            sum += v.x * wv.x + v.y * wv.y + v.z * wv.z + v.w * wv.w;
        }
        out[id] = 1.f / (1.f + expf(-sum));
    }
}

// ---------------- launch ----------------------------------------------------
extern "C" void kernel_launch(void* const* d_in, const int* in_sizes, int n_in,
                              void* d_out, int out_size)
{
    (void)in_sizes; (void)n_in; (void)out_size;
    const float* features = (const float*)d_in[0];
    const float* coord_w  = (const float*)d_in[1];
    const float* coord_b  = (const float*)d_in[2];
    const float* bn1_g = (const float*)d_in[3];
    const float* bn1_b = (const float*)d_in[4];
    const float* bn1_m = (const float*)d_in[5];
    const float* bn1_v = (const float*)d_in[6];
    const float* off_w = (const float*)d_in[7];
    const float* off_b = (const float*)d_in[8];
    const float* dc_w  = (const float*)d_in[9];
    const float* bn2_g = (const float*)d_in[10];
    const float* bn2_b = (const float*)d_in[11];
    const float* bn2_m = (const float*)d_in[12];
    const float* bn2_v = (const float*)d_in[13];
    const float* r1_w  = (const float*)d_in[14];
    const float* bn3_g = (const float*)d_in[15];
    const float* bn3_b = (const float*)d_in[16];
    const float* bn3_m = (const float*)d_in[17];
    const float* bn3_v = (const float*)d_in[18];
    const float* r2_w  = (const float*)d_in[19];
    const float* bn4_g = (const float*)d_in[20];
    const float* bn4_b = (const float*)d_in[21];
    const float* bn4_m = (const float*)d_in[22];
    const float* bn4_v = (const float*)d_in[23];
    const float* out_w = (const float*)d_in[24];
    const float* out_b = (const float*)d_in[25];

    float *wc, *wo, *wd, *wr1, *wr2, *bufA, *bufB, *offb;
    cudaGetSymbolAddress((void**)&wc,   g_wc);
    cudaGetSymbolAddress((void**)&wo,   g_wo);
    cudaGetSymbolAddress((void**)&wd,   g_wd);
    cudaGetSymbolAddress((void**)&wr1,  g_wr1);
    cudaGetSymbolAddress((void**)&wr2,  g_wr2);
    cudaGetSymbolAddress((void**)&bufA, g_bufA);
    cudaGetSymbolAddress((void**)&bufB, g_bufB);
    cudaGetSymbolAddress((void**)&offb, g_off);

    // weight transposes (tiny)
    transpose_w<<<(9*258*64 + 255) / 256, 256>>>(coord_w, wc, 64, 258, 64);
    transpose_w<<<(9*64*24  + 255) / 256, 256>>>(off_w,   wo, 18,  64, 24);
    transpose_w<<<(9*64*64  + 255) / 256, 256>>>(dc_w,    wd, 64,  64, 64);
    transpose_w<<<(9*64*64  + 255) / 256, 256>>>(r1_w,   wr1, 64,  64, 64);
    transpose_w<<<(9*64*64  + 255) / 256, 256>>>(r2_w,   wr2, 64,  64, 64);

    dim3 grid(WW / 16, HH / 8, BQ);

    // 1) coord conv + bn1 + relu -> bufA
    conv3x3<256, 258, 64, 64, 1><<<grid, 256>>>(
        features, 256, wc, bn1_g, bn1_b, bn1_m, bn1_v, bufA, 64, coord_b);

    // 2) offset conv + bias -> offb
    conv3x3<64, 64, 24, 18, 2><<<grid, 256>>>(
        bufA, 64, wo, off_b, nullptr, nullptr, nullptr, offb, 18, nullptr);

    // 3) deform conv + bn2 + relu -> bufB
    deform_kernel<<<NPIX / 128, 128>>>(bufA, offb, wd, bn2_g, bn2_b, bn2_m, bn2_v, bufB);

    // 4) r1 conv + bn3 + relu -> bufA
    conv3x3<64, 64, 64, 64, 0><<<grid, 256>>>(
        bufB, 64, wr1, bn3_g, bn3_b, bn3_m, bn3_v, bufA, 64, nullptr);

    // 5) r2 conv + bn4 + relu -> bufB
    conv3x3<64, 64, 64, 64, 0><<<grid, 256>>>(
        bufA, 64, wr2, bn4_g, bn4_b, bn4_m, bn4_v, bufB, 64, nullptr);

    // 6) 1x1 conv + sigmoid -> out
    out_kernel<<<(NPIX + 255) / 256, 256>>>(bufB, out_w, out_b, (float*)d_out);
}

// round 15
// speedup vs baseline: 1.0962x; 1.0962x over previous
#include <cuda_runtime.h>
#include <math.h>

#define BQ 8
#define HH 96
#define WW 96
#define NPIX (BQ*HH*WW)

// ---------------- scratch (device globals; no allocation allowed) ----------
__device__ float g_wc [9*258*64];   // coord conv weights   [t][ci][oc]
__device__ float g_wo [9*64*20];    // offset conv weights  [t][ci][ocp] (oc padded 18->20)
__device__ float g_wd [9*64*64];    // deform weights       [t][ci][oc]
__device__ float g_wr1[9*64*64];
__device__ float g_wr2[9*64*64];
__device__ float g_bufA[NPIX*64];
__device__ float g_bufB[NPIX*64];
__device__ float g_off [NPIX*18];

// ---------------- packed f32x2 helpers (Blackwell FFMA2 via PTX) -----------
__device__ __forceinline__ unsigned long long pack2(float v) {
    unsigned long long r;
    asm("mov.b64 %0, {%1, %1};" : "=l"(r) : "f"(v));
    return r;
}
__device__ __forceinline__ void fma2(unsigned long long& d,
                                     unsigned long long a, unsigned long long b) {
    asm("fma.rn.f32x2 %0, %1, %2, %3;" : "=l"(d) : "l"(a), "l"(b), "l"(d));
}
__device__ __forceinline__ void unpack2(unsigned long long p, float& lo, float& hi) {
    asm("mov.b64 {%0, %1}, %2;" : "=f"(lo), "=f"(hi) : "l"(p));
}

// ---------------- fused weight transpose: OIHW -> [t][ci][ocp], 1 launch ---
__global__ void transpose_all(const float* __restrict__ s0, const float* __restrict__ s1,
                              const float* __restrict__ s2, const float* __restrict__ s3,
                              const float* __restrict__ s4,
                              float* __restrict__ d0, float* __restrict__ d1,
                              float* __restrict__ d2, float* __restrict__ d3,
                              float* __restrict__ d4)
{
    const int n0 = 9*258*64, n1 = 9*64*20, n2 = 9*64*64;
    const int total = n0 + n1 + 3*n2;
    for (int i = blockIdx.x * blockDim.x + threadIdx.x; i < total;
         i += gridDim.x * blockDim.x) {
        int idx = i;
        const float* src; float* dst; int OC, IC, OCP;
        if (idx < n0)               { src = s0; dst = d0; OC = 64; IC = 258; OCP = 64; }
        else if ((idx -= n0) < n1)  { src = s1; dst = d1; OC = 18; IC = 64;  OCP = 20; }
        else if ((idx -= n1) < n2)  { src = s2; dst = d2; OC = 64; IC = 64;  OCP = 64; }
        else if ((idx -= n2) < n2)  { src = s3; dst = d3; OC = 64; IC = 64;  OCP = 64; }
        else     { idx -= n2;         src = s4; dst = d4; OC = 64; IC = 64;  OCP = 64; }
        int ocp  = idx % OCP;
        int rest = idx / OCP;
        int ci   = rest % IC;
        int t    = rest / IC;
        dst[idx] = (ocp < OC) ? src[(ocp * IC + ci) * 9 + t] : 0.0f;
    }
}

// ---------------- generic 3x3 conv, NHWC, tiled ----------------------------
// MODE 0: bn+relu   MODE 1: coordconv (+coord taps +bias +bn +relu)   MODE 2: +bias only
template<int CINLOOP, int CINT, int COUTP, int COUT, int MODE>
__global__ void __launch_bounds__(128) conv3x3(
    const float* __restrict__ in, int in_stride,
    const float* __restrict__ wT,                 // [9][CINT][COUTP]
    const float* __restrict__ p0, const float* __restrict__ p1,
    const float* __restrict__ p2, const float* __restrict__ p3,
    float* __restrict__ out, int out_stride,
    const float* __restrict__ cbias)
{
    __shared__ float patch[10 * 18 * 36];         // 8x16 tile + halo, 32ch, stride 36
    __shared__ float ws[2][32 * COUTP];           // ping-pong per-tap weights

    const int b  = blockIdx.z;
    const int h0 = blockIdx.y * 8;
    const int w0 = blockIdx.x * 16;
    const int tid = threadIdx.x;
    const int lh = tid >> 4;
    const int lw = tid & 15;

    unsigned long long acc2[COUTP / 2];
#pragma unroll
    for (int i = 0; i < COUTP / 2; ++i) acc2[i] = 0ull;

    for (int c0 = 0; c0 < CINLOOP; c0 += 32) {
        // ---- load 10x18x32 input patch (zero padded), stride-36 rows ----
        for (int p = tid; p < 180; p += 128) {
            int ph = p / 18, pw = p - ph * 18;
            int gh = h0 - 1 + ph, gw = w0 - 1 + pw;
            float4* dst = (float4*)&patch[p * 36];
            if ((unsigned)gh < (unsigned)HH && (unsigned)gw < (unsigned)WW) {
                const float4* src4 =
                    (const float4*)(in + ((b * HH + gh) * WW + gw) * in_stride + c0);
#pragma unroll
                for (int i = 0; i < 8; ++i) dst[i] = src4[i];
            } else {
#pragma unroll
                for (int i = 0; i < 8; ++i)
                    dst[i] = make_float4(0.f, 0.f, 0.f, 0.f);
            }
        }
        // ---- stage tap-0 weights into buffer 0 ----
        for (int i = tid * 4; i < 32 * COUTP; i += 128 * 4) {
            *(float4*)&ws[0][i] = *(const float4*)&wT[(0 * CINT + c0) * COUTP + i];
        }
        __syncthreads();

        for (int t = 0; t < 9; ++t) {
            // prefetch next tap's weights into the other buffer (overlaps FFMA2)
            if (t < 8) {
                for (int i = tid * 4; i < 32 * COUTP; i += 128 * 4) {
                    *(float4*)&ws[(t + 1) & 1][i] =
                        *(const float4*)&wT[((t + 1) * CINT + c0) * COUTP + i];
                }
            }
            const int ky = t / 3, kx = t - ky * 3;
            const float4* pr4 =
                (const float4*)&patch[((lh + ky) * 18 + (lw + kx)) * 36];
            const float* wbuf = ws[t & 1];
#pragma unroll
            for (int g = 0; g < 8; ++g) {         // 4 input channels per LDS.128
                float4 v4 = pr4[g];
                float vv[4] = {v4.x, v4.y, v4.z, v4.w};
#pragma unroll
                for (int c = 0; c < 4; ++c) {
                    unsigned long long v2 = pack2(vv[c]);
                    const ulonglong2* w2 =
                        (const ulonglong2*)&wbuf[(4 * g + c) * COUTP];
#pragma unroll
                    for (int j = 0; j < COUTP / 4; ++j) {
                        ulonglong2 wv = w2[j];    // 4 weights = 2 packed pairs
                        fma2(acc2[2 * j + 0], v2, wv.x);
                        fma2(acc2[2 * j + 1], v2, wv.y);
                    }
                }
            }
            __syncthreads();   // publish prefetched tap; drain before buffer reuse
        }
    }

    float acc[COUTP];
#pragma unroll
    for (int j = 0; j < COUTP / 2; ++j) unpack2(acc2[j], acc[2 * j], acc[2 * j + 1]);

    const int h = h0 + lh, w = w0 + lw;

    if constexpr (MODE == 1) {
        // analytic coord channels: ci=256 -> xx, ci=257 -> yy (zero-padded)
#pragma unroll
        for (int t = 0; t < 9; ++t) {
            int ky = t / 3, kx = t - ky * 3;
            int gh = h + ky - 1, gw = w + kx - 1;
            bool inb = (unsigned)gh < (unsigned)HH && (unsigned)gw < (unsigned)WW;
            float xxv = inb ? (-1.f + (2.f / 95.f) * (float)gw) : 0.f;
            float yyv = inb ? (-1.f + (2.f / 95.f) * (float)gh) : 0.f;
            const float* wx = &wT[(t * CINT + 256) * COUTP];
            const float* wy = wx + COUTP;
#pragma unroll
            for (int oc = 0; oc < COUTP; ++oc)
                acc[oc] += xxv * wx[oc] + yyv * wy[oc];
        }
    }

    float* op = out + ((b * HH + h) * WW + w) * out_stride;
#pragma unroll
    for (int oc = 0; oc < COUT; ++oc) {
        float a = acc[oc];
        if constexpr (MODE == 1) a += cbias[oc];
        float r;
        if constexpr (MODE == 2) {
            r = a + p0[oc];  // bias only
        } else {
            float inv = p0[oc] * rsqrtf(p3[oc] + 1e-5f);
            r = a * inv + (p1[oc] - p2[oc] * inv);
            r = fmaxf(r, 0.f);
        }
        op[oc] = r;
    }
}

// ---------------- deformable conv (bilinear gather + per-tap GEMM) ---------
__global__ void __launch_bounds__(128) deform_kernel(
    const float* __restrict__ x1, const float* __restrict__ off,
    const float* __restrict__ wT,  // [9][64][64]
    const float* __restrict__ bg, const float* __restrict__ bb,
    const float* __restrict__ bm, const float* __restrict__ bv,
    float* __restrict__ out)
{
    __shared__ float ws[2][64 * 64];               // ping-pong per-tap weights
    const int id = blockIdx.x * 128 + threadIdx.x;   // exactly NPIX threads
    const int w = id % WW;
    const int rest = id / WW;
    const int h = rest % HH;
    const int b = rest / HH;

    unsigned long long acc2[32];
#pragma unroll
    for (int i = 0; i < 32; ++i) acc2[i] = 0ull;

    const float* offp = off + id * 18;

    // stage tap-0 weights
    for (int i = threadIdx.x * 4; i < 4096; i += 512)
        *(float4*)&ws[0][i] = *(const float4*)&wT[i];
    __syncthreads();

    for (int k = 0; k < 9; ++k) {
        // prefetch next tap (overlaps gather + GEMM)
        if (k < 8) {
            for (int i = threadIdx.x * 4; i < 4096; i += 512)
                *(float4*)&ws[(k + 1) & 1][i] =
                    *(const float4*)&wT[(k + 1) * 4096 + i];
        }

        float oy = offp[2 * k + 0];
        float ox = offp[2 * k + 1];
        float py = (float)h + (float)(k / 3 - 1) + oy;
        float px = (float)w + (float)(k % 3 - 1) + ox;
        float y0 = floorf(py), x0 = floorf(px);

        unsigned long long s2[32];   // 64 gathered/weighted channels, packed
#pragma unroll
        for (int i = 0; i < 32; ++i) s2[i] = 0ull;

#pragma unroll
        for (int corner = 0; corner < 4; ++corner) {
            int dy = corner >> 1, dx = corner & 1;
            float yy = y0 + (float)dy, xx = x0 + (float)dx;
            float wgt = (1.f - fabsf(py - yy)) * (1.f - fabsf(px - xx));
            int iy = (int)yy, ix = (int)xx;
            if (iy >= 0 && iy < HH && ix >= 0 && ix < WW && wgt > 0.f) {
                unsigned long long wg2 = pack2(wgt);
                const ulonglong2* src =
                    (const ulonglong2*)(x1 + ((b * HH + iy) * WW + ix) * 64);
#pragma unroll
                for (int j = 0; j < 16; ++j) {
                    ulonglong2 v = src[j];
                    fma2(s2[2 * j + 0], wg2, v.x);
                    fma2(s2[2 * j + 1], wg2, v.y);
                }
            }
        }

        const float* wbuf = ws[k & 1];
#pragma unroll
        for (int cp = 0; cp < 32; ++cp) {        // pairs of input channels
            float va, vb;
            unpack2(s2[cp], va, vb);
            unsigned long long a2 = pack2(va);
            unsigned long long b2 = pack2(vb);
            const ulonglong2* wa = (const ulonglong2*)&wbuf[(2 * cp + 0) * 64];
            const ulonglong2* wb = (const ulonglong2*)&wbuf[(2 * cp + 1) * 64];
#pragma unroll
            for (int j = 0; j < 16; ++j) {
                ulonglong2 wva = wa[j];
                ulonglong2 wvb = wb[j];
                fma2(acc2[2 * j + 0], a2, wva.x);
                fma2(acc2[2 * j + 1], a2, wva.y);
                fma2(acc2[2 * j + 0], b2, wvb.x);
                fma2(acc2[2 * j + 1], b2, wvb.y);
            }
        }
        __syncthreads();   // publish prefetched tap; drain before buffer reuse
    }

    float acc[64];
#pragma unroll
    for (int j = 0; j < 32; ++j) unpack2(acc2[j], acc[2 * j], acc[2 * j + 1]);

    float* op = out + id * 64;
#pragma unroll
    for (int q = 0; q < 16; ++q) {
        float4 r4;
        float* rr = (float*)&r4;
#pragma unroll
        for (int c = 0; c < 4; ++c) {
            int oc = 4 * q + c;
            float inv = bg[oc] * rsqrtf(bv[oc] + 1e-5f);
            float r = acc[oc] * inv + (bb[oc] - bm[oc] * inv);
            rr[c] = fmaxf(r, 0.f);
        }
        ((float4*)op)[q] = r4;
    }
}

// ---------------- 1x1 conv + sigmoid ---------------------------------------
__global__ void out_kernel(const float* __restrict__ x, const float* __restrict__ ow,
                           const float* __restrict__ ob, float* __restrict__ out)
{
    __shared__ float wsh[64];
    if (threadIdx.x < 64) wsh[threadIdx.x] = ow[threadIdx.x];
    __syncthreads();
    int id = blockIdx.x * blockDim.x + threadIdx.x;
    if (id < NPIX) {
        const float4* xp = (const float4*)(x + id * 64);
        float sum = ob[0];
#pragma unroll
        for (int j = 0; j < 16; ++j) {
            float4 v = xp[j];
            float4 wv = ((float4*)wsh)[j];
            sum += v.x * wv.x + v.y * wv.y + v.z * wv.z + v.w * wv.w;
        }
        out[id] = 1.f / (1.f + expf(-sum));
    }
}

// ---------------- launch ----------------------------------------------------
extern "C" void kernel_launch(void* const* d_in, const int* in_sizes, int n_in,
                              void* d_out, int out_size)
{
    (void)in_sizes; (void)n_in; (void)out_size;
    const float* features = (const float*)d_in[0];
    const float* coord_w  = (const float*)d_in[1];
    const float* coord_b  = (const float*)d_in[2];
    const float* bn1_g = (const float*)d_in[3];
    const float* bn1_b = (const float*)d_in[4];
    const float* bn1_m = (const float*)d_in[5];
    const float* bn1_v = (const float*)d_in[6];
    const float* off_w = (const float*)d_in[7];
    const float* off_b = (const float*)d_in[8];
    const float* dc_w  = (const float*)d_in[9];
    const float* bn2_g = (const float*)d_in[10];
    const float* bn2_b = (const float*)d_in[11];
    const float* bn2_m = (const float*)d_in[12];
    const float* bn2_v = (const float*)d_in[13];
    const float* r1_w  = (const float*)d_in[14];
    const float* bn3_g = (const float*)d_in[15];
    const float* bn3_b = (const float*)d_in[16];
    const float* bn3_m = (const float*)d_in[17];
    const float* bn3_v = (const float*)d_in[18];
    const float* r2_w  = (const float*)d_in[19];
    const float* bn4_g = (const float*)d_in[20];
    const float* bn4_b = (const float*)d_in[21];
    const float* bn4_m = (const float*)d_in[22];
    const float* bn4_v = (const float*)d_in[23];
    const float* out_w = (const float*)d_in[24];
    const float* out_b = (const float*)d_in[25];

    float *wc, *wo, *wd, *wr1, *wr2, *bufA, *bufB, *offb;
    cudaGetSymbolAddress((void**)&wc,   g_wc);
    cudaGetSymbolAddress((void**)&wo,   g_wo);
    cudaGetSymbolAddress((void**)&wd,   g_wd);
    cudaGetSymbolAddress((void**)&wr1,  g_wr1);
    cudaGetSymbolAddress((void**)&wr2,  g_wr2);
    cudaGetSymbolAddress((void**)&bufA, g_bufA);
    cudaGetSymbolAddress((void**)&bufB, g_bufB);
    cudaGetSymbolAddress((void**)&offb, g_off);

    // fused weight transposes (1 launch)
    transpose_all<<<512, 256>>>(coord_w, off_w, dc_w, r1_w, r2_w,
                                wc, wo, wd, wr1, wr2);

    dim3 grid(WW / 16, HH / 8, BQ);

    // 1) coord conv + bn1 + relu -> bufA
    conv3x3<256, 258, 64, 64, 1><<<grid, 128>>>(
        features, 256, wc, bn1_g, bn1_b, bn1_m, bn1_v, bufA, 64, coord_b);

    // 2) offset conv + bias -> offb
    conv3x3<64, 64, 20, 18, 2><<<grid, 128>>>(
        bufA, 64, wo, off_b, nullptr, nullptr, nullptr, offb, 18, nullptr);

    // 3) deform conv + bn2 + relu -> bufB
    deform_kernel<<<NPIX / 128, 128>>>(bufA, offb, wd, bn2_g, bn2_b, bn2_m, bn2_v, bufB);

    // 4) r1 conv + bn3 + relu -> bufA
    conv3x3<64, 64, 64, 64, 0><<<grid, 128>>>(
        bufB, 64, wr1, bn3_g, bn3_b, bn3_m, bn3_v, bufA, 64, nullptr);

    // 5) r2 conv + bn4 + relu -> bufB
    conv3x3<64, 64, 64, 64, 0><<<grid, 128>>>(
        bufA, 64, wr2, bn4_g, bn4_b, bn4_m, bn4_v, bufB, 64, nullptr);

    // 6) 1x1 conv + sigmoid -> out
    out_kernel<<<(NPIX + 255) / 256, 256>>>(bufB, out_w, out_b, (float*)d_out);
}

// round 16
// speedup vs baseline: 1.1895x; 1.0850x over previous
#include <cuda_runtime.h>
#include <math.h>

#define BQ 8
#define HH 96
#define WW 96
#define NPIX (BQ*HH*WW)

// ---------------- scratch (device globals; no allocation allowed) ----------
__device__ float g_wc [9*258*64];   // coord conv weights   [t][ci][oc]
__device__ float g_wo [9*64*20];    // offset conv weights  [t][ci][ocp] (oc padded 18->20)
__device__ float g_wd [9*64*64];    // deform weights       [t][ci][oc]
__device__ float g_wr1[9*64*64];
__device__ float g_wr2[9*64*64];
__device__ float g_bufA[NPIX*64];
__device__ float g_bufB[NPIX*64];
__device__ float g_off [NPIX*18];

// ---------------- packed f32x2 helpers (Blackwell FFMA2 via PTX) -----------
__device__ __forceinline__ unsigned long long pack2(float v) {
    unsigned long long r;
    asm("mov.b64 %0, {%1, %1};" : "=l"(r) : "f"(v));
    return r;
}
__device__ __forceinline__ void fma2(unsigned long long& d,
                                     unsigned long long a, unsigned long long b) {
    asm("fma.rn.f32x2 %0, %1, %2, %3;" : "=l"(d) : "l"(a), "l"(b), "l"(d));
}
__device__ __forceinline__ void unpack2(unsigned long long p, float& lo, float& hi) {
    asm("mov.b64 {%0, %1}, %2;" : "=f"(lo), "=f"(hi) : "l"(p));
}

// ---------------- fused weight transpose: OIHW -> [t][ci][ocp], 1 launch ---
__global__ void transpose_all(const float* __restrict__ s0, const float* __restrict__ s1,
                              const float* __restrict__ s2, const float* __restrict__ s3,
                              const float* __restrict__ s4,
                              float* __restrict__ d0, float* __restrict__ d1,
                              float* __restrict__ d2, float* __restrict__ d3,
                              float* __restrict__ d4)
{
    const int n0 = 9*258*64, n1 = 9*64*20, n2 = 9*64*64;
    const int total = n0 + n1 + 3*n2;
    for (int i = blockIdx.x * blockDim.x + threadIdx.x; i < total;
         i += gridDim.x * blockDim.x) {
        int idx = i;
        const float* src; float* dst; int OC, IC, OCP;
        if (idx < n0)               { src = s0; dst = d0; OC = 64; IC = 258; OCP = 64; }
        else if ((idx -= n0) < n1)  { src = s1; dst = d1; OC = 18; IC = 64;  OCP = 20; }
        else if ((idx -= n1) < n2)  { src = s2; dst = d2; OC = 64; IC = 64;  OCP = 64; }
        else if ((idx -= n2) < n2)  { src = s3; dst = d3; OC = 64; IC = 64;  OCP = 64; }
        else     { idx -= n2;         src = s4; dst = d4; OC = 64; IC = 64;  OCP = 64; }
        int ocp  = idx % OCP;
        int rest = idx / OCP;
        int ci   = rest % IC;
        int t    = rest / IC;
        dst[idx] = (ocp < OC) ? src[(ocp * IC + ci) * 9 + t] : 0.0f;
    }
}

// ---------------- generic 3x3 conv, NHWC, tiled ----------------------------
// MODE 0: bn+relu   MODE 1: coordconv (+coord taps +bias +bn +relu)   MODE 2: +bias only
template<int CINLOOP, int CINT, int COUTP, int COUT, int MODE>
__global__ void __launch_bounds__(128) conv3x3(
    const float* __restrict__ in, int in_stride,
    const float* __restrict__ wT,                 // [9][CINT][COUTP]
    const float* __restrict__ p0, const float* __restrict__ p1,
    const float* __restrict__ p2, const float* __restrict__ p3,
    float* __restrict__ out, int out_stride,
    const float* __restrict__ cbias)
{
    __shared__ float patch[10 * 18 * 36];         // 8x16 tile + halo, 32ch, stride 36
    __shared__ float ws[2][32 * COUTP];           // ping-pong per-tap weights

    const int b  = blockIdx.z;
    const int h0 = blockIdx.y * 8;
    const int w0 = blockIdx.x * 16;
    const int tid = threadIdx.x;
    const int lh = tid >> 4;
    const int lw = tid & 15;

    unsigned long long acc2[COUTP / 2];
#pragma unroll
    for (int i = 0; i < COUTP / 2; ++i) acc2[i] = 0ull;

    for (int c0 = 0; c0 < CINLOOP; c0 += 32) {
        // ---- load 10x18x32 input patch (zero padded), stride-36 rows ----
        for (int p = tid; p < 180; p += 128) {
            int ph = p / 18, pw = p - ph * 18;
            int gh = h0 - 1 + ph, gw = w0 - 1 + pw;
            float4* dst = (float4*)&patch[p * 36];
            if ((unsigned)gh < (unsigned)HH && (unsigned)gw < (unsigned)WW) {
                const float4* src4 =
                    (const float4*)(in + ((b * HH + gh) * WW + gw) * in_stride + c0);
#pragma unroll
                for (int i = 0; i < 8; ++i) dst[i] = src4[i];
            } else {
#pragma unroll
                for (int i = 0; i < 8; ++i)
                    dst[i] = make_float4(0.f, 0.f, 0.f, 0.f);
            }
        }
        // ---- stage tap-0 weights into buffer 0 ----
        for (int i = tid * 4; i < 32 * COUTP; i += 128 * 4) {
            *(float4*)&ws[0][i] = *(const float4*)&wT[(0 * CINT + c0) * COUTP + i];
        }
        __syncthreads();

        for (int t = 0; t < 9; ++t) {
            // prefetch next tap's weights into the other buffer (overlaps FFMA2)
            if (t < 8) {
                for (int i = tid * 4; i < 32 * COUTP; i += 128 * 4) {
                    *(float4*)&ws[(t + 1) & 1][i] =
                        *(const float4*)&wT[((t + 1) * CINT + c0) * COUTP + i];
                }
            }
            const int ky = t / 3, kx = t - ky * 3;
            const float4* pr4 =
                (const float4*)&patch[((lh + ky) * 18 + (lw + kx)) * 36];
            const float* wbuf = ws[t & 1];
#pragma unroll
            for (int g = 0; g < 8; ++g) {         // 4 input channels per LDS.128
                float4 v4 = pr4[g];
                float vv[4] = {v4.x, v4.y, v4.z, v4.w};
#pragma unroll
                for (int c = 0; c < 4; ++c) {
                    unsigned long long v2 = pack2(vv[c]);
                    const ulonglong2* w2 =
                        (const ulonglong2*)&wbuf[(4 * g + c) * COUTP];
#pragma unroll
                    for (int j = 0; j < COUTP / 4; ++j) {
                        ulonglong2 wv = w2[j];    // 4 weights = 2 packed pairs
                        fma2(acc2[2 * j + 0], v2, wv.x);
                        fma2(acc2[2 * j + 1], v2, wv.y);
                    }
                }
            }
            __syncthreads();   // publish prefetched tap; drain before buffer reuse
        }
    }

    float acc[COUTP];
#pragma unroll
    for (int j = 0; j < COUTP / 2; ++j) unpack2(acc2[j], acc[2 * j], acc[2 * j + 1]);

    const int h = h0 + lh, w = w0 + lw;

    if constexpr (MODE == 1) {
        // analytic coord channels: ci=256 -> xx, ci=257 -> yy (zero-padded)
#pragma unroll
        for (int t = 0; t < 9; ++t) {
            int ky = t / 3, kx = t - ky * 3;
            int gh = h + ky - 1, gw = w + kx - 1;
            bool inb = (unsigned)gh < (unsigned)HH && (unsigned)gw < (unsigned)WW;
            float xxv = inb ? (-1.f + (2.f / 95.f) * (float)gw) : 0.f;
            float yyv = inb ? (-1.f + (2.f / 95.f) * (float)gh) : 0.f;
            const float* wx = &wT[(t * CINT + 256) * COUTP];
            const float* wy = wx + COUTP;
#pragma unroll
            for (int oc = 0; oc < COUTP; ++oc)
                acc[oc] += xxv * wx[oc] + yyv * wy[oc];
        }
    }

    float* op = out + ((b * HH + h) * WW + w) * out_stride;
#pragma unroll
    for (int oc = 0; oc < COUT; ++oc) {
        float a = acc[oc];
        if constexpr (MODE == 1) a += cbias[oc];
        float r;
        if constexpr (MODE == 2) {
            r = a + p0[oc];  // bias only
        } else {
            float inv = p0[oc] * rsqrtf(p3[oc] + 1e-5f);
            r = a * inv + (p1[oc] - p2[oc] * inv);
            r = fmaxf(r, 0.f);
        }
        op[oc] = r;
    }
}

// ---------------- deformable conv v2: cooperative gather + 2-px GEMM -------
// 128 threads, 128 pixels per block. Dynamic smem layout (floats):
//   [0, 8192)          ws ping-pong  2 x 64x64 weights
//   [8192, 16896)      sg: 128 rows x 68 (gathered 64-ch vectors)
//   [16896, 17408)     cw: corner weights  [4][128]
//   [17408, 17920)     cp: corner row offsets (int) [4][128]
#define DEF_SMEM_FLOATS 17920
__global__ void __launch_bounds__(128) deform_kernel(
    const float* __restrict__ x1, const float* __restrict__ off,
    const float* __restrict__ wT,  // [9][64][64]
    const float* __restrict__ bg, const float* __restrict__ bb,
    const float* __restrict__ bm, const float* __restrict__ bv,
    float* __restrict__ out)
{
    extern __shared__ float smem[];
    float* ws = smem;                  // 2*4096
    float* sg = smem + 8192;           // 128*68
    float* cw = smem + 16896;          // 4*128
    int*   cp = (int*)(smem + 17408);  // 4*128

    const int tid  = threadIdx.x;
    const int pix0 = blockIdx.x * 128;
    const int id   = pix0 + tid;                 // own pixel for phase A
    const int w    = id % WW;
    const int rest = id / WW;
    const int h    = rest % HH;
    const int b    = rest / HH;

    // GEMM mapping: pixel pair (2*pp, 2*pp+1), oc half oh
    const int pp = tid & 63;
    const int oh = tid >> 6;

    unsigned long long accA[16], accB[16];       // 2 px x 32 oc
#pragma unroll
    for (int i = 0; i < 16; ++i) { accA[i] = 0ull; accB[i] = 0ull; }

    const float* offp = off + id * 18;

    // stage tap-0 weights
    for (int i = tid * 4; i < 4096; i += 512)
        *(float4*)&ws[i] = *(const float4*)&wT[i];
    __syncthreads();

    for (int k = 0; k < 9; ++k) {
        // prefetch next tap's weights (other buffer)
        if (k < 8) {
            for (int i = tid * 4; i < 4096; i += 512)
                *(float4*)&ws[((k + 1) & 1) * 4096 + i] =
                    *(const float4*)&wT[(k + 1) * 4096 + i];
        }

        // ---- phase A: corner data for own pixel ----
        {
            float oy = offp[2 * k + 0];
            float ox = offp[2 * k + 1];
            float py = (float)h + (float)(k / 3 - 1) + oy;
            float px = (float)w + (float)(k % 3 - 1) + ox;
            float y0 = floorf(py), x0 = floorf(px);
#pragma unroll
            for (int corner = 0; corner < 4; ++corner) {
                int dy = corner >> 1, dx = corner & 1;
                float yy = y0 + (float)dy, xx = x0 + (float)dx;
                float wgt = (1.f - fabsf(py - yy)) * (1.f - fabsf(px - xx));
                int iy = (int)yy, ix = (int)xx;
                bool ok = (iy >= 0) && (iy < HH) && (ix >= 0) && (ix < WW) && (wgt > 0.f);
                cw[corner * 128 + tid] = ok ? wgt : 0.f;
                cp[corner * 128 + tid] = ok ? ((b * HH + iy) * WW + ix) * 64 : 0;
            }
        }
        __syncthreads();

        // ---- phase B: cooperative coalesced gather ----
        {
            const int g = tid & 7;                // channel group (8 floats)
            const int qb = tid >> 3;              // 0..15
#pragma unroll
            for (int i = 0; i < 8; ++i) {
                int q = qb + 16 * i;              // pixel 0..127
                unsigned long long t2[4] = {0ull, 0ull, 0ull, 0ull};
#pragma unroll
                for (int corner = 0; corner < 4; ++corner) {
                    float wgt = cw[corner * 128 + q];
                    int base  = cp[corner * 128 + q];
                    unsigned long long wg2 = pack2(wgt);
                    const ulonglong2* src = (const ulonglong2*)(x1 + base + g * 8);
                    ulonglong2 v0 = src[0];
                    ulonglong2 v1 = src[1];
                    fma2(t2[0], wg2, v0.x); fma2(t2[1], wg2, v0.y);
                    fma2(t2[2], wg2, v1.x); fma2(t2[3], wg2, v1.y);
                }
                ulonglong2* dst = (ulonglong2*)&sg[q * 68 + g * 8];
                dst[0] = make_ulonglong2(t2[0], t2[1]);
                dst[1] = make_ulonglong2(t2[2], t2[3]);
            }
        }
        __syncthreads();

        // ---- phase C: GEMM, 2 pixels x 32 oc per thread ----
        {
            const float* wbuf = ws + (k & 1) * 4096 + oh * 32;
            const float4* vr0 = (const float4*)&sg[(2 * pp + 0) * 68];
            const float4* vr1 = (const float4*)&sg[(2 * pp + 1) * 68];
#pragma unroll
            for (int q = 0; q < 16; ++q) {
                float4 a4 = vr0[q];
                float4 b4 = vr1[q];
                float av[4] = {a4.x, a4.y, a4.z, a4.w};
                float bv[4] = {b4.x, b4.y, b4.z, b4.w};
#pragma unroll
                for (int c = 0; c < 4; ++c) {
                    unsigned long long va = pack2(av[c]);
                    unsigned long long vb = pack2(bv[c]);
                    const ulonglong2* w2 =
                        (const ulonglong2*)&wbuf[(4 * q + c) * 64];
#pragma unroll
                    for (int j = 0; j < 8; ++j) {
                        ulonglong2 wv = w2[j];
                        fma2(accA[2 * j + 0], va, wv.x);
                        fma2(accA[2 * j + 1], va, wv.y);
                        fma2(accB[2 * j + 0], vb, wv.x);
                        fma2(accB[2 * j + 1], vb, wv.y);
                    }
                }
            }
        }
        __syncthreads();   // sg/cw/cp/ws-buffer reuse safe for next tap
    }

    // ---- epilogue: bn + relu, 2 pixels x 32 oc ----
#pragma unroll
    for (int e = 0; e < 2; ++e) {
        unsigned long long* acc2 = e ? accB : accA;
        float* op = out + (pix0 + 2 * pp + e) * 64 + oh * 32;
#pragma unroll
        for (int q = 0; q < 8; ++q) {            // 8 x float4 = 32 oc
            float v0, v1, v2, v3;
            unpack2(acc2[2 * q + 0], v0, v1);
            unpack2(acc2[2 * q + 1], v2, v3);
            float vs[4] = {v0, v1, v2, v3};
            float4 r4;
            float* rr = (float*)&r4;
#pragma unroll
            for (int c = 0; c < 4; ++c) {
                int oc = oh * 32 + 4 * q + c;
                float inv = bg[oc] * rsqrtf(bv[oc] + 1e-5f);
                float r = vs[c] * inv + (bb[oc] - bm[oc] * inv);
                rr[c] = fmaxf(r, 0.f);
            }
            ((float4*)op)[q] = r4;
        }
    }
}

// ---------------- 1x1 conv + sigmoid ---------------------------------------
__global__ void out_kernel(const float* __restrict__ x, const float* __restrict__ ow,
                           const float* __restrict__ ob, float* __restrict__ out)
{
    __shared__ float wsh[64];
    if (threadIdx.x < 64) wsh[threadIdx.x] = ow[threadIdx.x];
    __syncthreads();
    int id = blockIdx.x * blockDim.x + threadIdx.x;
    if (id < NPIX) {
        const float4* xp = (const float4*)(x + id * 64);
        float sum = ob[0];
#pragma unroll
        for (int j = 0; j < 16; ++j) {
            float4 v = xp[j];
            float4 wv = ((float4*)wsh)[j];
            sum += v.x * wv.x + v.y * wv.y + v.z * wv.z + v.w * wv.w;
        }
        out[id] = 1.f / (1.f + expf(-sum));
    }
}

// ---------------- launch ----------------------------------------------------
extern "C" void kernel_launch(void* const* d_in, const int* in_sizes, int n_in,
                              void* d_out, int out_size)
{
    (void)in_sizes; (void)n_in; (void)out_size;
    const float* features = (const float*)d_in[0];
    const float* coord_w  = (const float*)d_in[1];
    const float* coord_b  = (const float*)d_in[2];
    const float* bn1_g = (const float*)d_in[3];
    const float* bn1_b = (const float*)d_in[4];
    const float* bn1_m = (const float*)d_in[5];
    const float* bn1_v = (const float*)d_in[6];
    const float* off_w = (const float*)d_in[7];
    const float* off_b = (const float*)d_in[8];
    const float* dc_w  = (const float*)d_in[9];
    const float* bn2_g = (const float*)d_in[10];
    const float* bn2_b = (const float*)d_in[11];
    const float* bn2_m = (const float*)d_in[12];
    const float* bn2_v = (const float*)d_in[13];
    const float* r1_w  = (const float*)d_in[14];
    const float* bn3_g = (const float*)d_in[15];
    const float* bn3_b = (const float*)d_in[16];
    const float* bn3_m = (const float*)d_in[17];
    const float* bn3_v = (const float*)d_in[18];
    const float* r2_w  = (const float*)d_in[19];
    const float* bn4_g = (const float*)d_in[20];
    const float* bn4_b = (const float*)d_in[21];
    const float* bn4_m = (const float*)d_in[22];
    const float* bn4_v = (const float*)d_in[23];
    const float* out_w = (const float*)d_in[24];
    const float* out_b = (const float*)d_in[25];

    float *wc, *wo, *wd, *wr1, *wr2, *bufA, *bufB, *offb;
    cudaGetSymbolAddress((void**)&wc,   g_wc);
    cudaGetSymbolAddress((void**)&wo,   g_wo);
    cudaGetSymbolAddress((void**)&wd,   g_wd);
    cudaGetSymbolAddress((void**)&wr1,  g_wr1);
    cudaGetSymbolAddress((void**)&wr2,  g_wr2);
    cudaGetSymbolAddress((void**)&bufA, g_bufA);
    cudaGetSymbolAddress((void**)&bufB, g_bufB);
    cudaGetSymbolAddress((void**)&offb, g_off);

    // opt-in to >48KB dynamic smem for deform (idempotent, immediate, no alloc)
    cudaFuncSetAttribute(deform_kernel,
                         cudaFuncAttributeMaxDynamicSharedMemorySize,
                         DEF_SMEM_FLOATS * 4);

    // fused weight transposes (1 launch)
    transpose_all<<<512, 256>>>(coord_w, off_w, dc_w, r1_w, r2_w,
                                wc, wo, wd, wr1, wr2);

    dim3 grid(WW / 16, HH / 8, BQ);

    // 1) coord conv + bn1 + relu -> bufA
    conv3x3<256, 258, 64, 64, 1><<<grid, 128>>>(
        features, 256, wc, bn1_g, bn1_b, bn1_m, bn1_v, bufA, 64, coord_b);

    // 2) offset conv + bias -> offb
    conv3x3<64, 64, 20, 18, 2><<<grid, 128>>>(
        bufA, 64, wo, off_b, nullptr, nullptr, nullptr, offb, 18, nullptr);

    // 3) deform conv + bn2 + relu -> bufB
    deform_kernel<<<NPIX / 128, 128, DEF_SMEM_FLOATS * 4>>>(
        bufA, offb, wd, bn2_g, bn2_b, bn2_m, bn2_v, bufB);

    // 4) r1 conv + bn3 + relu -> bufA
    conv3x3<64, 64, 64, 64, 0><<<grid, 128>>>(
        bufB, 64, wr1, bn3_g, bn3_b, bn3_m, bn3_v, bufA, 64, nullptr);

    // 5) r2 conv + bn4 + relu -> bufB
    conv3x3<64, 64, 64, 64, 0><<<grid, 128>>>(
        bufA, 64, wr2, bn4_g, bn4_b, bn4_m, bn4_v, bufB, 64, nullptr);

    // 6) 1x1 conv + sigmoid -> out
    out_kernel<<<(NPIX + 255) / 256, 256>>>(bufB, out_w, out_b, (float*)d_out);
}